// round 16
// baseline (speedup 1.0000x reference)
#include <cuda_runtime.h>
#include <cuda_bf16.h>

#define N_NODES 100000
#define N_EDGES 1600000
#define IN_DIM  256
#define HIDDEN  64

#define EDGE_PAIRS (N_EDGES / 2)   // 800000 int2 loads
#define DEG_BLOCKS 3125            // bid % 5 == 0 -> deg-only block
#define DOT_BLOCKS 12500           // other bids   -> dot-only block
#define MAIN_BLOCKS (DEG_BLOCKS + DOT_BLOCKS)   // 15625
#define PREP_BLOCKS 33             // 32 blocks u (warp/output), block 32 -> c

// Scratch (__device__ globals; zero at module load; k_out re-zeros for replay)
__device__ __align__(16) float g_u[IN_DIM];    // W @ w2
__device__ float g_c;                           // b.w2 + b2
__device__ __align__(16) float2 g_sd[N_NODES];  // .x = raw s[v], .y = edge count
__device__ __align__(16) float  g_t[N_NODES];   // aggregated normalized ss[src]

// K1: warp per output element. Block i (<32), warp w -> u[i*8+w].
//     Block 32, warp 0 computes c = b.w2 + b2.
__global__ void __launch_bounds__(256) k_prep(
        const float* __restrict__ W, const float* __restrict__ b,
        const float* __restrict__ w2, const float* __restrict__ b2) {
    const int wid  = threadIdx.x >> 5;
    const int lane = threadIdx.x & 31;
    float wa = w2[lane];
    float wb = w2[lane + 32];
    if (blockIdx.x < 32) {
        int row = blockIdx.x * 8 + wid;          // 0..255
        const float* wr = W + (size_t)row * HIDDEN;
        float acc = wr[lane] * wa + wr[lane + 32] * wb;
#pragma unroll
        for (int o = 16; o; o >>= 1) acc += __shfl_xor_sync(0xffffffffu, acc, o);
        if (lane == 0) g_u[row] = acc;
    } else if (wid == 0) {
        float acc = b[lane] * wa + b[lane + 32] * wb;
#pragma unroll
        for (int o = 16; o; o >>= 1) acc += __shfl_xor_sync(0xffffffffu, acc, o);
        if (lane == 0) g_c = acc + b2[0];
    }
}

// K2 (PDL secondary of prep): block-specialized.
//   bid % 5 == 0  (3125 blocks): deg-only — one int2 of dst, two REDs, exit.
//     Never touches g_u, never syncs -> exits fast, LTS-bound work striped
//     across every wave while dot blocks stream DRAM.
//   else          (12500 blocks): pure dot — prefetch x, sync on prep, FMA.
__global__ void __launch_bounds__(256) k_dotdeg(
        const float* __restrict__ x, const int* __restrict__ dst) {
    const int tid = threadIdx.x;
    const int bid = blockIdx.x;

    if (bid % 5 == 0) {
        int pair = (bid / 5) * 256 + tid;        // 0..799999 exactly
        int2 p = ((const int2*)dst)[pair];
        if ((unsigned)p.x < (unsigned)N_NODES) atomicAdd(&g_sd[p.x].y, 1.0f);
        if ((unsigned)p.y < (unsigned)N_NODES) atomicAdd(&g_sd[p.y].y, 1.0f);
        return;
    }

    const int dot_ord = bid - (bid / 5) - 1;     // 0..12499
    const int node = dot_ord * 8 + (tid >> 5);   // warp per node
    const int lane = tid & 31;

    const float4* xp = (const float4*)(x + (size_t)node * IN_DIM);
    float4 a0 = __ldcs(&xp[lane]);
    float4 a1 = __ldcs(&xp[lane + 32]);

#if __CUDA_ARCH__ >= 900
    cudaGridDependencySynchronize();   // wait for k_prep's g_u
#endif

    const float4* up = (const float4*)g_u;
    float4 u0 = up[lane];
    float4 u1 = up[lane + 32];
    float acc = a0.x*u0.x + a0.y*u0.y + a0.z*u0.z + a0.w*u0.w
              + a1.x*u1.x + a1.y*u1.y + a1.z*u1.z + a1.w*u1.w;
#pragma unroll
    for (int o = 16; o; o >>= 1) acc += __shfl_xor_sync(0xffffffffu, acc, o);
    if (lane == 0) g_sd[node].x = acc;   // RAW
}

// K3 (PDL secondary of dotdeg): prefetch src/dst indices, sync, gather + RED.
__global__ void __launch_bounds__(256) k_scatter(const int* __restrict__ src,
                                                 const int* __restrict__ dst) {
    int i = blockIdx.x * 256 + threadIdx.x;
    int2 s = make_int2(-1, -1), d = make_int2(-1, -1);
    if (i < EDGE_PAIRS) {
        s = ((const int2*)src)[i];
        d = ((const int2*)dst)[i];
    }
#if __CUDA_ARCH__ >= 900
    cudaGridDependencySynchronize();   // wait for k_dotdeg's g_sd
#endif
    if (i < EDGE_PAIRS) {
        float v0 = 0.f, v1 = 0.f;
        if ((unsigned)s.x < (unsigned)N_NODES) {
            float2 sd = g_sd[s.x];
            v0 = sd.x * rsqrtf(1.0f + sd.y);
        }
        if ((unsigned)s.y < (unsigned)N_NODES) {
            float2 sd = g_sd[s.y];
            v1 = sd.x * rsqrtf(1.0f + sd.y);
        }
        if ((unsigned)d.x < (unsigned)N_NODES) atomicAdd(&g_t[d.x], v0);
        if ((unsigned)d.y < (unsigned)N_NODES) atomicAdd(&g_t[d.y], v1);
    }
}

// K4 (PDL secondary of scatter, sync-at-top): 1 node/thread.
__global__ void __launch_bounds__(256) k_out(float* __restrict__ out) {
#if __CUDA_ARCH__ >= 900
    cudaGridDependencySynchronize();
#endif
    int v = blockIdx.x * 256 + threadIdx.x;
    if (v < N_NODES) {
        float2 sd = g_sd[v];
        float  t  = g_t[v];
        float di = rsqrtf(1.0f + sd.y);
        float z  = di * (t + sd.x * di) + g_c;
        out[v] = 1.0f / (1.0f + __expf(-z));
        g_sd[v] = make_float2(sd.x, 0.f);   // reset degree
        g_t[v]  = 0.f;
    }
}

static void launch_pdl(const void* fn, dim3 grid, dim3 block, void** args) {
    cudaLaunchConfig_t cfg = {};
    cfg.gridDim = grid;
    cfg.blockDim = block;
    cfg.dynamicSmemBytes = 0;
    cfg.stream = (cudaStream_t)0;
    cudaLaunchAttribute attr[1];
    attr[0].id = cudaLaunchAttributeProgrammaticStreamSerialization;
    attr[0].val.programmaticStreamSerializationAllowed = 1;
    cfg.attrs = attr;
    cfg.numAttrs = 1;
    cudaLaunchKernelExC(&cfg, fn, args);
}

extern "C" void kernel_launch(void* const* d_in, const int* in_sizes, int n_in,
                              void* d_out, int out_size) {
    const float* x   = (const float*)d_in[0];
    const int*   ei  = (const int*)d_in[1];   // [2, N_EDGES], materialized as int32
    const float* W   = (const float*)d_in[2];
    const float* b   = (const float*)d_in[3];
    const float* w2  = (const float*)d_in[4];
    const float* b2  = (const float*)d_in[5];
    float*       out = (float*)d_out;

    const int* src = ei;
    const int* dst = ei + N_EDGES;

    k_prep<<<PREP_BLOCKS, 256>>>(W, b, w2, b2);

    {
        void* args[] = {(void*)&x, (void*)&dst};
        launch_pdl((const void*)k_dotdeg, dim3(MAIN_BLOCKS), dim3(256), args);
    }
    {
        void* args[] = {(void*)&src, (void*)&dst};
        launch_pdl((const void*)k_scatter,
                   dim3((EDGE_PAIRS + 255) / 256), dim3(256), args);
    }
    {
        void* args[] = {(void*)&out};
        launch_pdl((const void*)k_out,
                   dim3((N_NODES + 255) / 256), dim3(256), args);
    }
}